// round 2
// baseline (speedup 1.0000x reference)
#include <cuda_runtime.h>
#include <cuda_bf16.h>

#define NN 100000
#define NE 1600000

// -------- scratch (static device memory; no allocations) --------
__device__ int   d_deg[NN];
__device__ int   d_off[NN + 1];
__device__ int   d_cur[NN];
__device__ float d_dinv[NN];
__device__ int   d_csr[NE];
__device__ float d_bufA[NN * 64];
__device__ float d_bufB[NN * 64];
__device__ float2 d_g[NN];
__device__ float d_C[96];   // [0..39] P0, [40..79] P1, [80..91] scalars

// -------- degree count --------
__global__ void k_zero()
{
    int i = blockIdx.x * 256 + threadIdx.x;
    if (i < NN) d_deg[i] = 0;
}

__global__ void k_count(const int* __restrict__ dst)
{
    int e = blockIdx.x * 256 + threadIdx.x;
    if (e < NE) atomicAdd(&d_deg[dst[e]], 1);
}

// -------- single-block scan: offsets, cursor, dinv --------
__global__ void k_scan()
{
    __shared__ int ssum[1024];
    int t = threadIdx.x;
    const int CH = (NN + 1023) / 1024;   // 98
    int beg = t * CH;
    int end = beg + CH; if (end > NN) end = NN;
    int s = 0;
    for (int i = beg; i < end; i++) s += d_deg[i];
    ssum[t] = s;
    __syncthreads();
    // Hillis-Steele inclusive scan
    for (int o = 1; o < 1024; o <<= 1) {
        int v = (t >= o) ? ssum[t - o] : 0;
        __syncthreads();
        ssum[t] += v;
        __syncthreads();
    }
    int run = ssum[t] - s;   // exclusive prefix
    for (int i = beg; i < end; i++) {
        d_off[i] = run;
        d_cur[i] = run;
        int dg = d_deg[i];
        run += dg;
        d_dinv[i] = rsqrtf((float)(dg + 1));   // +1 for self loop
    }
    if (t == 1023) d_off[NN] = run;
}

// -------- CSR fill --------
__global__ void k_fill(const int* __restrict__ src, const int* __restrict__ dst)
{
    int e = blockIdx.x * 256 + threadIdx.x;
    if (e < NE) {
        int p = atomicAdd(&d_cur[dst[e]], 1);
        d_csr[p] = src[e];
    }
}

// -------- GEMM: Z[n][:] = dinv[n] * (X[n][:] @ W) ; X,W,Z all 64-wide --------
__global__ void __launch_bounds__(256) k_gemm(const float* __restrict__ X,
                                              const float* __restrict__ W,
                                              float* __restrict__ Z)
{
    __shared__ float Ws[64 * 64];
    for (int i = threadIdx.x; i < 4096; i += 256) Ws[i] = W[i];
    __syncthreads();

    int n = blockIdx.x * 256 + threadIdx.x;
    if (n >= NN) return;

    float acc[64];
#pragma unroll
    for (int j = 0; j < 64; j++) acc[j] = 0.f;

    const float4* xr = (const float4*)(X + (size_t)n * 64);
#pragma unroll 2
    for (int k4 = 0; k4 < 16; k4++) {
        float4 xv = xr[k4];
#pragma unroll
        for (int kk = 0; kk < 4; kk++) {
            float xs = (kk == 0) ? xv.x : (kk == 1) ? xv.y : (kk == 2) ? xv.z : xv.w;
            const float4* wr = (const float4*)(Ws + (k4 * 4 + kk) * 64);
#pragma unroll
            for (int j4 = 0; j4 < 16; j4++) {
                float4 w = wr[j4];
                acc[j4 * 4 + 0] += xs * w.x;
                acc[j4 * 4 + 1] += xs * w.y;
                acc[j4 * 4 + 2] += xs * w.z;
                acc[j4 * 4 + 3] += xs * w.w;
            }
        }
    }

    float dv = d_dinv[n];
    float4* zr = (float4*)(Z + (size_t)n * 64);
#pragma unroll
    for (int j4 = 0; j4 < 16; j4++) {
        float4 v;
        v.x = dv * acc[j4 * 4 + 0];
        v.y = dv * acc[j4 * 4 + 1];
        v.z = dv * acc[j4 * 4 + 2];
        v.w = dv * acc[j4 * 4 + 3];
        zr[j4] = v;
    }
}

// -------- aggregation layer 1: H[d] = relu(dinv[d]*(Z[d] + sum Z[src]) + b) --------
__global__ void __launch_bounds__(256) k_agg1(const float* __restrict__ Z,
                                              const float* __restrict__ b,
                                              float* __restrict__ H)
{
    int warp = (blockIdx.x * 256 + threadIdx.x) >> 5;
    int lane = threadIdx.x & 31;
    if (warp >= NN) return;
    int n = warp;
    int beg = d_off[n], end = d_off[n + 1];

    float2 acc = *(const float2*)(Z + (size_t)n * 64 + 2 * lane);   // self loop
    for (int base = beg; base < end; base += 32) {
        int cnt = end - base; if (cnt > 32) cnt = 32;
        int sv = (base + lane < end) ? d_csr[base + lane] : 0;
#pragma unroll 4
        for (int i = 0; i < cnt; i++) {
            int s = __shfl_sync(0xffffffffu, sv, i);
            float2 v = *(const float2*)(Z + (size_t)s * 64 + 2 * lane);
            acc.x += v.x; acc.y += v.y;
        }
    }
    float dv = d_dinv[n];
    float2 bb = *(const float2*)(b + 2 * lane);
    float2 h;
    h.x = fmaxf(dv * acc.x + bb.x, 0.f);
    h.y = fmaxf(dv * acc.y + bb.y, 0.f);
    *(float2*)(H + (size_t)n * 64 + 2 * lane) = h;
}

// -------- aggregation layer 2 + fused g[n] = h2[n] @ fcW1[0:64,:] --------
__global__ void __launch_bounds__(256) k_agg2(const float* __restrict__ Z,
                                              const float* __restrict__ b,
                                              const float* __restrict__ fcW1)
{
    int warp = (blockIdx.x * 256 + threadIdx.x) >> 5;
    int lane = threadIdx.x & 31;
    if (warp >= NN) return;
    int n = warp;
    int beg = d_off[n], end = d_off[n + 1];

    float2 acc = *(const float2*)(Z + (size_t)n * 64 + 2 * lane);
    for (int base = beg; base < end; base += 32) {
        int cnt = end - base; if (cnt > 32) cnt = 32;
        int sv = (base + lane < end) ? d_csr[base + lane] : 0;
#pragma unroll 4
        for (int i = 0; i < cnt; i++) {
            int s = __shfl_sync(0xffffffffu, sv, i);
            float2 v = *(const float2*)(Z + (size_t)s * 64 + 2 * lane);
            acc.x += v.x; acc.y += v.y;
        }
    }
    float dv = d_dinv[n];
    float2 bb = *(const float2*)(b + 2 * lane);
    float hx = dv * acc.x + bb.x;   // no relu on layer 2
    float hy = dv * acc.y + bb.y;

    // g_j = sum_feat h2[feat]*fcW1[feat*2+j]; this lane owns feats 2*lane, 2*lane+1
    float4 w = *(const float4*)(fcW1 + 4 * lane);
    float g0 = hx * w.x + hy * w.z;
    float g1 = hx * w.y + hy * w.w;
#pragma unroll
    for (int o = 16; o > 0; o >>= 1) {
        g0 += __shfl_xor_sync(0xffffffffu, g0, o);
        g1 += __shfl_xor_sync(0xffffffffu, g1, o);
    }
    if (lane == 0) d_g[n] = make_float2(g0, g1);
}

// -------- tiny table prep: P0/P1 + scalar constants --------
__global__ void k_prep(const float* __restrict__ emb0, const float* __restrict__ emb1,
                       const float* __restrict__ fcW1, const float* __restrict__ fcb1,
                       const float* __restrict__ fcW2, const float* __restrict__ fcb2)
{
    int t = threadIdx.x;
    if (t < 40) {
        int i = t >> 1, j = t & 1;
        float s = 0.f;
        for (int k = 0; k < 32; k++) s += emb0[i * 32 + k] * fcW1[(66 + k) * 2 + j];
        d_C[t] = s;
    } else if (t < 80) {
        int u = t - 40;
        int i = u >> 1, j = u & 1;
        float s = 0.f;
        for (int k = 0; k < 32; k++) s += emb1[i * 32 + k] * fcW1[(98 + k) * 2 + j];
        d_C[t] = s;
    } else if (t < 92) {
        int u = t - 80;
        float v;
        if (u < 4)       v = fcW1[128 + u];     // rows 64,65 (vl weights)
        else if (u < 6)  v = fcb1[u - 4];
        else if (u < 10) v = fcW2[u - 6];
        else             v = fcb2[u - 10];
        d_C[t] = v;
    }
}

// -------- edge head: per-edge MLP + log_softmax --------
__global__ void __launch_bounds__(256) k_edge(const int* __restrict__ src,
                                              const int* __restrict__ dst,
                                              const int* __restrict__ attr,
                                              float2* __restrict__ out)
{
    __shared__ float Cs[92];
    if (threadIdx.x < 92) Cs[threadIdx.x] = d_C[threadIdx.x];
    __syncthreads();

    int e = blockIdx.x * 256 + threadIdx.x;
    if (e >= NE) return;

    int s = src[e], d = dst[e];
    int a0 = attr[e];
    int a1 = attr[NE + e];
    int a2 = attr[2 * NE + e];
    int a3 = attr[3 * NE + e];

    float2 gs = d_g[s], gd = d_g[d];
    float f0 = (float)a0, f1 = (float)a1;

    float u0 = gs.x - gd.x + f0 * Cs[80] + f1 * Cs[82] + Cs[a2 * 2]     + Cs[40 + a3 * 2]     + Cs[84];
    float u1 = gs.y - gd.y + f0 * Cs[81] + f1 * Cs[83] + Cs[a2 * 2 + 1] + Cs[40 + a3 * 2 + 1] + Cs[85];
    u0 = fmaxf(u0, 0.f);
    u1 = fmaxf(u1, 0.f);

    float v0 = u0 * Cs[86] + u1 * Cs[88] + Cs[90];
    float v1 = u0 * Cs[87] + u1 * Cs[89] + Cs[91];

    float m = fmaxf(v0, v1);
    float lse = m + logf(expf(v0 - m) + expf(v1 - m));
    out[e] = make_float2(v0 - lse, v1 - lse);
}

extern "C" void kernel_launch(void* const* d_in, const int* in_sizes, int n_in,
                              void* d_out, int out_size)
{
    const float* x    = (const float*)d_in[0];
    const int*   ei   = (const int*)  d_in[1];   // [0..NE)=src, [NE..2NE)=dst
    const int*   ea   = (const int*)  d_in[2];   // 4 rows of NE
    const float* W1   = (const float*)d_in[3];
    const float* b1   = (const float*)d_in[4];
    const float* W2   = (const float*)d_in[5];
    const float* b2   = (const float*)d_in[6];
    const float* emb0 = (const float*)d_in[7];
    const float* emb1 = (const float*)d_in[8];
    const float* fcW1 = (const float*)d_in[9];
    const float* fcb1 = (const float*)d_in[10];
    const float* fcW2 = (const float*)d_in[11];
    const float* fcb2 = (const float*)d_in[12];

    const int* src = ei;
    const int* dst = ei + NE;

    int gbN  = (NN + 255) / 256;
    int gbE  = (NE + 255) / 256;
    int gbW  = (NN * 32 + 255) / 256;   // warp per node

    k_zero <<<gbN, 256>>>();
    k_count<<<gbE, 256>>>(dst);
    k_scan <<<1, 1024>>>();
    k_fill <<<gbE, 256>>>(src, dst);
    k_prep <<<1, 128>>>(emb0, emb1, fcW1, fcb1, fcW2, fcb2);

    k_gemm <<<gbN, 256>>>(x, W1, d_bufA);
    k_agg1 <<<gbW, 256>>>(d_bufA, b1, d_bufB);
    k_gemm <<<gbN, 256>>>(d_bufB, W2, d_bufA);
    k_agg2 <<<gbW, 256>>>(d_bufA, b2, fcW1);

    k_edge <<<gbE, 256>>>(src, dst, ea, (float2*)d_out);
}

// round 3
// speedup vs baseline: 1.1089x; 1.1089x over previous
#include <cuda_runtime.h>

#define NN 100000
#define NE 1600000
#define NB 98   // ceil(NN/1024)

// -------- static scratch (no allocations) --------
__device__ int    d_deg[NN];        // invariant: zero at kernel_launch entry (zeroed by scanC)
__device__ int    d_off[NN + 1];
__device__ int    d_cur[NN];
__device__ float  d_dinv[NN];
__device__ int    d_csr[NE];
__device__ float  d_csrw[NE];       // dinv[src] per CSR slot
__device__ float4 d_bufA[NN * 16];
__device__ float4 d_bufB[NN * 16];
__device__ float2 d_g[NN];
__device__ float  d_C[96];          // [0..39] P0, [40..79] P1, [80..91] scalars
__device__ int    d_part[NB];
__device__ int    d_poff[NB];

// -------- 1: degree count (d_deg starts at 0) --------
__global__ void k_count(const int* __restrict__ dst)
{
    int e = blockIdx.x * 256 + threadIdx.x;
    if (e < NE) atomicAdd(&d_deg[dst[e]], 1);
}

// -------- 2: per-1024-chunk partial sums (coalesced) --------
__global__ void k_scanA()
{
    __shared__ int sred[1024];
    int t = threadIdx.x;
    int i = blockIdx.x * 1024 + t;
    sred[t] = (i < NN) ? d_deg[i] : 0;
    __syncthreads();
#pragma unroll
    for (int o = 512; o > 0; o >>= 1) {
        if (t < o) sred[t] += sred[t + o];
        __syncthreads();
    }
    if (t == 0) d_part[blockIdx.x] = sred[0];
}

// -------- 3: scan the 98 partials + constant-table prep --------
__global__ void k_scanB(const float* __restrict__ emb0, const float* __restrict__ emb1,
                        const float* __restrict__ fcW1, const float* __restrict__ fcb1,
                        const float* __restrict__ fcW2, const float* __restrict__ fcb2)
{
    int t = threadIdx.x;
    if (t < 40) {
        int i = t >> 1, j = t & 1;
        float s = 0.f;
#pragma unroll
        for (int k = 0; k < 32; k++) s = fmaf(emb0[i * 32 + k], fcW1[(66 + k) * 2 + j], s);
        d_C[t] = s;
    } else if (t < 80) {
        int u = t - 40;
        int i = u >> 1, j = u & 1;
        float s = 0.f;
#pragma unroll
        for (int k = 0; k < 32; k++) s = fmaf(emb1[i * 32 + k], fcW1[(98 + k) * 2 + j], s);
        d_C[t] = s;
    } else if (t < 92) {
        int u = t - 80;
        float v;
        if (u < 4)       v = fcW1[128 + u];     // rows 64,65 (vl weights)
        else if (u < 6)  v = fcb1[u - 4];
        else if (u < 10) v = fcW2[u - 6];
        else             v = fcb2[u - 10];
        d_C[t] = v;
    }
    if (t == 127) {
        int run = 0;
#pragma unroll 7
        for (int i = 0; i < NB; i++) { int v = d_part[i]; d_poff[i] = run; run += v; }
        d_off[NN] = run;
    }
}

// -------- GEMM: Z[n][:] = X[n][:] @ W (64x64). 2 threads per node, 32 cols each --------
__global__ void __launch_bounds__(256) k_gemm(const float* __restrict__ X,
                                              const float* __restrict__ W,
                                              float* __restrict__ Z)
{
    __shared__ float Ws[4096];
    for (int i = threadIdx.x; i < 4096; i += 256) Ws[i] = W[i];
    __syncthreads();

    int idx = blockIdx.x * 256 + threadIdx.x;
    int n = idx >> 1, half = idx & 1;
    if (n >= NN) return;

    const float4* xr = (const float4*)(X + (size_t)n * 64);
    float acc[32];
#pragma unroll
    for (int j = 0; j < 32; j++) acc[j] = 0.f;

#pragma unroll 4
    for (int k4 = 0; k4 < 16; k4++) {
        float4 xv = xr[k4];
#pragma unroll
        for (int kk = 0; kk < 4; kk++) {
            float xs = (kk == 0) ? xv.x : (kk == 1) ? xv.y : (kk == 2) ? xv.z : xv.w;
            const float4* wr = (const float4*)(Ws + (k4 * 4 + kk) * 64 + half * 32);
#pragma unroll
            for (int j4 = 0; j4 < 8; j4++) {
                float4 w = wr[j4];
                acc[j4 * 4 + 0] = fmaf(xs, w.x, acc[j4 * 4 + 0]);
                acc[j4 * 4 + 1] = fmaf(xs, w.y, acc[j4 * 4 + 1]);
                acc[j4 * 4 + 2] = fmaf(xs, w.z, acc[j4 * 4 + 2]);
                acc[j4 * 4 + 3] = fmaf(xs, w.w, acc[j4 * 4 + 3]);
            }
        }
    }

    float4* zr = (float4*)(Z + (size_t)n * 64 + half * 32);
#pragma unroll
    for (int j4 = 0; j4 < 8; j4++)
        zr[j4] = make_float4(acc[j4 * 4], acc[j4 * 4 + 1], acc[j4 * 4 + 2], acc[j4 * 4 + 3]);
}

// -------- 5: offsets/cursor/dinv via block scan (coalesced) + re-zero d_deg --------
__global__ void k_scanC()
{
    __shared__ int swarp[32];
    int t = threadIdx.x, lane = t & 31, wid = t >> 5;
    int i = blockIdx.x * 1024 + t;
    int deg = (i < NN) ? d_deg[i] : 0;
    int v = deg;
#pragma unroll
    for (int o = 1; o < 32; o <<= 1) {
        int u = __shfl_up_sync(0xffffffffu, v, o);
        if (lane >= o) v += u;
    }
    if (lane == 31) swarp[wid] = v;
    __syncthreads();
    if (wid == 0) {
        int w = swarp[lane];
        int wv = w;
#pragma unroll
        for (int o = 1; o < 32; o <<= 1) {
            int u = __shfl_up_sync(0xffffffffu, wv, o);
            if (lane >= o) wv += u;
        }
        swarp[lane] = wv - w;   // exclusive prefix of warp sums
    }
    __syncthreads();
    if (i < NN) {
        int off = d_poff[blockIdx.x] + swarp[wid] + (v - deg);
        d_off[i] = off;
        d_cur[i] = off;
        d_dinv[i] = rsqrtf((float)(deg + 1));
        d_deg[i] = 0;   // restore invariant for next call
    }
}

// -------- 6: CSR fill (index + dinv[src] weight) --------
__global__ void k_fill(const int* __restrict__ src, const int* __restrict__ dst)
{
    int e = blockIdx.x * 256 + threadIdx.x;
    if (e < NE) {
        int s = src[e];
        int p = atomicAdd(&d_cur[dst[e]], 1);
        d_csr[p]  = s;
        d_csrw[p] = d_dinv[s];
    }
}

// -------- aggregation: out_d = dinv_d*(dinv_d*Z_d + sum dinv_s*Z_s) + b --------
// mode 0: relu -> H.   mode 1: fused g[n] = h2[n] @ fcW1[0:64,:]
__global__ void __launch_bounds__(256) k_agg(const float* __restrict__ Z,
                                             const float* __restrict__ bias,
                                             float* __restrict__ H,
                                             const float* __restrict__ fcW1,
                                             int mode)
{
    int gw = (blockIdx.x * 256 + threadIdx.x) >> 5;
    int lane = threadIdx.x & 31;
    if (gw >= NN) return;
    int n = gw;
    int beg = d_off[n], end = d_off[n + 1];
    float dv = d_dinv[n];

    float2 z = *(const float2*)(Z + (size_t)n * 64 + 2 * lane);
    float ax = dv * z.x, ay = dv * z.y;

    for (int base = beg; base < end; base += 32) {
        int k = base + lane;
        int   sv = (k < end) ? d_csr[k]  : 0;
        float wv = (k < end) ? d_csrw[k] : 0.f;
        int cnt = end - base; if (cnt > 32) cnt = 32;
        int j = 0;
        for (; j + 4 <= cnt; j += 4) {
            int s0 = __shfl_sync(0xffffffffu, sv, j);
            int s1 = __shfl_sync(0xffffffffu, sv, j + 1);
            int s2 = __shfl_sync(0xffffffffu, sv, j + 2);
            int s3 = __shfl_sync(0xffffffffu, sv, j + 3);
            float w0 = __shfl_sync(0xffffffffu, wv, j);
            float w1 = __shfl_sync(0xffffffffu, wv, j + 1);
            float w2 = __shfl_sync(0xffffffffu, wv, j + 2);
            float w3 = __shfl_sync(0xffffffffu, wv, j + 3);
            float2 v0 = *(const float2*)(Z + (size_t)s0 * 64 + 2 * lane);
            float2 v1 = *(const float2*)(Z + (size_t)s1 * 64 + 2 * lane);
            float2 v2 = *(const float2*)(Z + (size_t)s2 * 64 + 2 * lane);
            float2 v3 = *(const float2*)(Z + (size_t)s3 * 64 + 2 * lane);
            ax = fmaf(w0, v0.x, ax); ay = fmaf(w0, v0.y, ay);
            ax = fmaf(w1, v1.x, ax); ay = fmaf(w1, v1.y, ay);
            ax = fmaf(w2, v2.x, ax); ay = fmaf(w2, v2.y, ay);
            ax = fmaf(w3, v3.x, ax); ay = fmaf(w3, v3.y, ay);
        }
        for (; j < cnt; j++) {
            int   s = __shfl_sync(0xffffffffu, sv, j);
            float w = __shfl_sync(0xffffffffu, wv, j);
            float2 v = *(const float2*)(Z + (size_t)s * 64 + 2 * lane);
            ax = fmaf(w, v.x, ax); ay = fmaf(w, v.y, ay);
        }
    }

    float2 bb = *(const float2*)(bias + 2 * lane);
    float hx = fmaf(dv, ax, bb.x);
    float hy = fmaf(dv, ay, bb.y);

    if (mode == 0) {
        hx = fmaxf(hx, 0.f);
        hy = fmaxf(hy, 0.f);
        *(float2*)(H + (size_t)n * 64 + 2 * lane) = make_float2(hx, hy);
    } else {
        float4 w = *(const float4*)(fcW1 + 4 * lane);
        float g0 = fmaf(hx, w.x, hy * w.z);
        float g1 = fmaf(hx, w.y, hy * w.w);
#pragma unroll
        for (int o = 16; o > 0; o >>= 1) {
            g0 += __shfl_xor_sync(0xffffffffu, g0, o);
            g1 += __shfl_xor_sync(0xffffffffu, g1, o);
        }
        if (lane == 0) d_g[n] = make_float2(g0, g1);
    }
}

// -------- edge head: per-edge MLP + log_softmax --------
__global__ void __launch_bounds__(256) k_edge(const int* __restrict__ src,
                                              const int* __restrict__ dst,
                                              const int* __restrict__ attr,
                                              float2* __restrict__ out)
{
    __shared__ float Cs[92];
    if (threadIdx.x < 92) Cs[threadIdx.x] = d_C[threadIdx.x];
    __syncthreads();

    int e = blockIdx.x * 256 + threadIdx.x;
    if (e >= NE) return;

    int s = src[e], d = dst[e];
    int a0 = attr[e];
    int a1 = attr[NE + e];
    int a2 = attr[2 * NE + e];
    int a3 = attr[3 * NE + e];

    float2 gs = d_g[s], gd = d_g[d];
    float f0 = (float)a0, f1 = (float)a1;

    float u0 = gs.x - gd.x + f0 * Cs[80] + f1 * Cs[82] + Cs[a2 * 2]     + Cs[40 + a3 * 2]     + Cs[84];
    float u1 = gs.y - gd.y + f0 * Cs[81] + f1 * Cs[83] + Cs[a2 * 2 + 1] + Cs[40 + a3 * 2 + 1] + Cs[85];
    u0 = fmaxf(u0, 0.f);
    u1 = fmaxf(u1, 0.f);

    float v0 = u0 * Cs[86] + u1 * Cs[88] + Cs[90];
    float v1 = u0 * Cs[87] + u1 * Cs[89] + Cs[91];

    float m = fmaxf(v0, v1);
    float lse = m + __logf(__expf(v0 - m) + __expf(v1 - m));
    out[e] = make_float2(v0 - lse, v1 - lse);
}

extern "C" void kernel_launch(void* const* d_in, const int* in_sizes, int n_in,
                              void* d_out, int out_size)
{
    const float* x    = (const float*)d_in[0];
    const int*   ei   = (const int*)  d_in[1];
    const int*   ea   = (const int*)  d_in[2];
    const float* W1   = (const float*)d_in[3];
    const float* b1   = (const float*)d_in[4];
    const float* W2   = (const float*)d_in[5];
    const float* b2   = (const float*)d_in[6];
    const float* emb0 = (const float*)d_in[7];
    const float* emb1 = (const float*)d_in[8];
    const float* fcW1 = (const float*)d_in[9];
    const float* fcb1 = (const float*)d_in[10];
    const float* fcW2 = (const float*)d_in[11];
    const float* fcb2 = (const float*)d_in[12];

    const int* src = ei;
    const int* dst = ei + NE;

    int gbE = (NE + 255) / 256;
    int gbG = (2 * NN + 255) / 256;
    int gbW = (NN * 32 + 255) / 256;

    k_count<<<gbE, 256>>>(dst);
    k_scanA<<<NB, 1024>>>();
    k_scanB<<<1, 128>>>(emb0, emb1, fcW1, fcb1, fcW2, fcb2);
    k_gemm <<<gbG, 256>>>(x, W1, (float*)d_bufA);
    k_scanC<<<NB, 1024>>>();
    k_fill <<<gbE, 256>>>(src, dst);
    k_agg  <<<gbW, 256>>>((const float*)d_bufA, b1, (float*)d_bufB, fcW1, 0);
    k_gemm <<<gbG, 256>>>((const float*)d_bufB, W2, (float*)d_bufA);
    k_agg  <<<gbW, 256>>>((const float*)d_bufA, b2, nullptr, fcW1, 1);
    k_edge <<<gbE, 256>>>(src, dst, ea, (float2*)d_out);
}

// round 4
// speedup vs baseline: 1.1231x; 1.0128x over previous
#include <cuda_runtime.h>

#define NN 100000
#define NE 1600000
#define NB 98   // ceil(NN/1024)

// -------- static scratch (no allocations) --------
__device__ int    d_deg[NN];        // invariant: zero at kernel_launch entry (re-zeroed by scanC)
__device__ int    d_off[NN + 1];
__device__ int    d_cur[NN];
__device__ float  d_dinv[NN];
__device__ int    d_csr[NE];
__device__ float  d_csrw[NE];       // dinv[src] per CSR slot
__device__ float4 d_bufA[NN * 16];
__device__ float4 d_bufB[NN * 16];
__device__ float2 d_g[NN];
__device__ float  d_C[96];          // [0..39] P0, [40..79] P1, [80..91] scalars
__device__ int    d_part[NB];
__device__ int    d_poff[NB];

// -------- 1: degree count, 4 edges/thread (d_deg starts at 0) --------
__global__ void k_count(const int* __restrict__ dst)
{
    int base = (blockIdx.x * 256 + threadIdx.x) * 4;
    if (base < NE) {
        int4 d4 = *(const int4*)(dst + base);
        atomicAdd(&d_deg[d4.x], 1);
        atomicAdd(&d_deg[d4.y], 1);
        atomicAdd(&d_deg[d4.z], 1);
        atomicAdd(&d_deg[d4.w], 1);
    }
}

// -------- 2: per-1024-chunk partial sums --------
__global__ void k_scanA()
{
    __shared__ int sred[1024];
    int t = threadIdx.x;
    int i = blockIdx.x * 1024 + t;
    sred[t] = (i < NN) ? d_deg[i] : 0;
    __syncthreads();
#pragma unroll
    for (int o = 512; o > 0; o >>= 1) {
        if (t < o) sred[t] += sred[t + o];
        __syncthreads();
    }
    if (t == 0) d_part[blockIdx.x] = sred[0];
}

// -------- 3: scan the 98 partials + constant-table prep --------
__global__ void k_scanB(const float* __restrict__ emb0, const float* __restrict__ emb1,
                        const float* __restrict__ fcW1, const float* __restrict__ fcb1,
                        const float* __restrict__ fcW2, const float* __restrict__ fcb2)
{
    int t = threadIdx.x;
    if (t < 40) {
        int i = t >> 1, j = t & 1;
        float s = 0.f;
#pragma unroll
        for (int k = 0; k < 32; k++) s = fmaf(emb0[i * 32 + k], fcW1[(66 + k) * 2 + j], s);
        d_C[t] = s;
    } else if (t < 80) {
        int u = t - 40;
        int i = u >> 1, j = u & 1;
        float s = 0.f;
#pragma unroll
        for (int k = 0; k < 32; k++) s = fmaf(emb1[i * 32 + k], fcW1[(98 + k) * 2 + j], s);
        d_C[t] = s;
    } else if (t < 92) {
        int u = t - 80;
        float v;
        if (u < 4)       v = fcW1[128 + u];
        else if (u < 6)  v = fcb1[u - 4];
        else if (u < 10) v = fcW2[u - 6];
        else             v = fcb2[u - 10];
        d_C[t] = v;
    }
    if (t == 127) {
        int run = 0;
#pragma unroll 7
        for (int i = 0; i < NB; i++) { int v = d_part[i]; d_poff[i] = run; run += v; }
        d_off[NN] = run;
    }
}

// -------- GEMM: Z = X @ W (64x64). 2 threads/node. X row prefetched 8 float4 deep --------
__global__ void __launch_bounds__(256) k_gemm(const float* __restrict__ X,
                                              const float* __restrict__ W,
                                              float* __restrict__ Z)
{
    __shared__ float Ws[4096];
    {
        const float4* W4 = (const float4*)W;
        float4* Ws4 = (float4*)Ws;
        for (int i = threadIdx.x; i < 1024; i += 256) Ws4[i] = W4[i];
    }
    __syncthreads();

    int idx = blockIdx.x * 256 + threadIdx.x;
    int n = idx >> 1, half = idx & 1;
    if (n >= NN) return;

    const float4* xr = (const float4*)(X + (size_t)n * 64);
    float acc[32];
#pragma unroll
    for (int j = 0; j < 32; j++) acc[j] = 0.f;

#pragma unroll
    for (int hblk = 0; hblk < 2; hblk++) {
        // prefetch 8 independent float4 (MLP = 8)
        float4 xv[8];
#pragma unroll
        for (int i = 0; i < 8; i++) xv[i] = xr[hblk * 8 + i];
#pragma unroll
        for (int i = 0; i < 8; i++) {
            int k4 = hblk * 8 + i;
#pragma unroll
            for (int kk = 0; kk < 4; kk++) {
                float xs = (kk == 0) ? xv[i].x : (kk == 1) ? xv[i].y : (kk == 2) ? xv[i].z : xv[i].w;
                const float4* wr = (const float4*)(Ws + (k4 * 4 + kk) * 64 + half * 32);
#pragma unroll
                for (int j4 = 0; j4 < 8; j4++) {
                    float4 w = wr[j4];
                    acc[j4 * 4 + 0] = fmaf(xs, w.x, acc[j4 * 4 + 0]);
                    acc[j4 * 4 + 1] = fmaf(xs, w.y, acc[j4 * 4 + 1]);
                    acc[j4 * 4 + 2] = fmaf(xs, w.z, acc[j4 * 4 + 2]);
                    acc[j4 * 4 + 3] = fmaf(xs, w.w, acc[j4 * 4 + 3]);
                }
            }
        }
    }

    float4* zr = (float4*)(Z + (size_t)n * 64 + half * 32);
#pragma unroll
    for (int j4 = 0; j4 < 8; j4++)
        zr[j4] = make_float4(acc[j4 * 4], acc[j4 * 4 + 1], acc[j4 * 4 + 2], acc[j4 * 4 + 3]);
}

// -------- 5: offsets/cursor/dinv via block scan + re-zero d_deg --------
__global__ void k_scanC()
{
    __shared__ int swarp[32];
    int t = threadIdx.x, lane = t & 31, wid = t >> 5;
    int i = blockIdx.x * 1024 + t;
    int deg = (i < NN) ? d_deg[i] : 0;
    int v = deg;
#pragma unroll
    for (int o = 1; o < 32; o <<= 1) {
        int u = __shfl_up_sync(0xffffffffu, v, o);
        if (lane >= o) v += u;
    }
    if (lane == 31) swarp[wid] = v;
    __syncthreads();
    if (wid == 0) {
        int w = swarp[lane];
        int wv = w;
#pragma unroll
        for (int o = 1; o < 32; o <<= 1) {
            int u = __shfl_up_sync(0xffffffffu, wv, o);
            if (lane >= o) wv += u;
        }
        swarp[lane] = wv - w;
    }
    __syncthreads();
    if (i < NN) {
        int off = d_poff[blockIdx.x] + swarp[wid] + (v - deg);
        d_off[i] = off;
        d_cur[i] = off;
        d_dinv[i] = rsqrtf((float)(deg + 1));
        d_deg[i] = 0;
    }
}

// -------- 6: CSR fill, 4 edges/thread --------
__global__ void k_fill(const int* __restrict__ src, const int* __restrict__ dst)
{
    int base = (blockIdx.x * 256 + threadIdx.x) * 4;
    if (base < NE) {
        int4 s4 = *(const int4*)(src + base);
        int4 d4 = *(const int4*)(dst + base);
        float w0 = d_dinv[s4.x];
        float w1 = d_dinv[s4.y];
        float w2 = d_dinv[s4.z];
        float w3 = d_dinv[s4.w];
        int p0 = atomicAdd(&d_cur[d4.x], 1);
        int p1 = atomicAdd(&d_cur[d4.y], 1);
        int p2 = atomicAdd(&d_cur[d4.z], 1);
        int p3 = atomicAdd(&d_cur[d4.w], 1);
        d_csr[p0] = s4.x;  d_csrw[p0] = w0;
        d_csr[p1] = s4.y;  d_csrw[p1] = w1;
        d_csr[p2] = s4.z;  d_csrw[p2] = w2;
        d_csr[p3] = s4.w;  d_csrw[p3] = w3;
    }
}

// -------- aggregation: out_d = dinv_d*(dinv_d*Z_d + sum dinv_s*Z_s) + b --------
// mode 0: relu -> H.   mode 1: fused g[n] = h2[n] @ fcW1[0:64,:]
__global__ void __launch_bounds__(256) k_agg(const float* __restrict__ Z,
                                             const float* __restrict__ bias,
                                             float* __restrict__ H,
                                             const float* __restrict__ fcW1,
                                             int mode)
{
    int gw = (blockIdx.x * 256 + threadIdx.x) >> 5;
    int lane = threadIdx.x & 31;
    if (gw >= NN) return;
    int n = gw;
    int beg = d_off[n], end = d_off[n + 1];
    float dv = d_dinv[n];

    float2 z = *(const float2*)(Z + (size_t)n * 64 + 2 * lane);
    float ax = dv * z.x, ay = dv * z.y;

    for (int base = beg; base < end; base += 32) {
        int k = base + lane;
        int   sv = (k < end) ? d_csr[k]  : 0;
        float wv = (k < end) ? d_csrw[k] : 0.f;
        int cnt = end - base; if (cnt > 32) cnt = 32;
        int j = 0;
        // 8-wide batches: 8 independent gathers in flight
        for (; j + 8 <= cnt; j += 8) {
            float2 v[8];
            float  w[8];
#pragma unroll
            for (int i = 0; i < 8; i++) {
                int s = __shfl_sync(0xffffffffu, sv, j + i);
                w[i]  = __shfl_sync(0xffffffffu, wv, j + i);
                v[i]  = *(const float2*)(Z + (size_t)s * 64 + 2 * lane);
            }
#pragma unroll
            for (int i = 0; i < 8; i++) {
                ax = fmaf(w[i], v[i].x, ax);
                ay = fmaf(w[i], v[i].y, ay);
            }
        }
        // 4-wide batch
        if (j + 4 <= cnt) {
            float2 v[4];
            float  w[4];
#pragma unroll
            for (int i = 0; i < 4; i++) {
                int s = __shfl_sync(0xffffffffu, sv, j + i);
                w[i]  = __shfl_sync(0xffffffffu, wv, j + i);
                v[i]  = *(const float2*)(Z + (size_t)s * 64 + 2 * lane);
            }
#pragma unroll
            for (int i = 0; i < 4; i++) {
                ax = fmaf(w[i], v[i].x, ax);
                ay = fmaf(w[i], v[i].y, ay);
            }
            j += 4;
        }
        for (; j < cnt; j++) {
            int   s = __shfl_sync(0xffffffffu, sv, j);
            float w = __shfl_sync(0xffffffffu, wv, j);
            float2 v = *(const float2*)(Z + (size_t)s * 64 + 2 * lane);
            ax = fmaf(w, v.x, ax); ay = fmaf(w, v.y, ay);
        }
    }

    float2 bb = *(const float2*)(bias + 2 * lane);
    float hx = fmaf(dv, ax, bb.x);
    float hy = fmaf(dv, ay, bb.y);

    if (mode == 0) {
        hx = fmaxf(hx, 0.f);
        hy = fmaxf(hy, 0.f);
        *(float2*)(H + (size_t)n * 64 + 2 * lane) = make_float2(hx, hy);
    } else {
        float4 w = *(const float4*)(fcW1 + 4 * lane);
        float g0 = fmaf(hx, w.x, hy * w.z);
        float g1 = fmaf(hx, w.y, hy * w.w);
#pragma unroll
        for (int o = 16; o > 0; o >>= 1) {
            g0 += __shfl_xor_sync(0xffffffffu, g0, o);
            g1 += __shfl_xor_sync(0xffffffffu, g1, o);
        }
        if (lane == 0) d_g[n] = make_float2(g0, g1);
    }
}

// -------- edge head: 4 edges/thread, MLP across the 8 d_g gathers --------
__global__ void __launch_bounds__(256) k_edge(const int* __restrict__ src,
                                              const int* __restrict__ dst,
                                              const int* __restrict__ attr,
                                              float4* __restrict__ out)
{
    __shared__ float Cs[92];
    if (threadIdx.x < 92) Cs[threadIdx.x] = d_C[threadIdx.x];
    __syncthreads();

    int base = (blockIdx.x * 256 + threadIdx.x) * 4;
    if (base >= NE) return;

    int4 s4 = *(const int4*)(src + base);
    int4 d4 = *(const int4*)(dst + base);
    int4 a0 = *(const int4*)(attr + base);
    int4 a1 = *(const int4*)(attr + NE + base);
    int4 a2 = *(const int4*)(attr + 2 * NE + base);
    int4 a3 = *(const int4*)(attr + 3 * NE + base);

    // 8 independent gathers
    float2 gs0 = d_g[s4.x], gs1 = d_g[s4.y], gs2 = d_g[s4.z], gs3 = d_g[s4.w];
    float2 gd0 = d_g[d4.x], gd1 = d_g[d4.y], gd2 = d_g[d4.z], gd3 = d_g[d4.w];

    float r[8];
    int aa0[4] = {a0.x, a0.y, a0.z, a0.w};
    int aa1[4] = {a1.x, a1.y, a1.z, a1.w};
    int aa2[4] = {a2.x, a2.y, a2.z, a2.w};
    int aa3[4] = {a3.x, a3.y, a3.z, a3.w};
    float2 gss[4] = {gs0, gs1, gs2, gs3};
    float2 gdd[4] = {gd0, gd1, gd2, gd3};

#pragma unroll
    for (int i = 0; i < 4; i++) {
        float f0 = (float)aa0[i], f1 = (float)aa1[i];
        float u0 = gss[i].x - gdd[i].x + f0 * Cs[80] + f1 * Cs[82]
                 + Cs[aa2[i] * 2]     + Cs[40 + aa3[i] * 2]     + Cs[84];
        float u1 = gss[i].y - gdd[i].y + f0 * Cs[81] + f1 * Cs[83]
                 + Cs[aa2[i] * 2 + 1] + Cs[40 + aa3[i] * 2 + 1] + Cs[85];
        u0 = fmaxf(u0, 0.f);
        u1 = fmaxf(u1, 0.f);
        float v0 = u0 * Cs[86] + u1 * Cs[88] + Cs[90];
        float v1 = u0 * Cs[87] + u1 * Cs[89] + Cs[91];
        float m = fmaxf(v0, v1);
        float lse = m + __logf(__expf(v0 - m) + __expf(v1 - m));
        r[i * 2]     = v0 - lse;
        r[i * 2 + 1] = v1 - lse;
    }

    out[base >> 1]       = make_float4(r[0], r[1], r[2], r[3]);
    out[(base >> 1) + 1] = make_float4(r[4], r[5], r[6], r[7]);
}

extern "C" void kernel_launch(void* const* d_in, const int* in_sizes, int n_in,
                              void* d_out, int out_size)
{
    const float* x    = (const float*)d_in[0];
    const int*   ei   = (const int*)  d_in[1];
    const int*   ea   = (const int*)  d_in[2];
    const float* W1   = (const float*)d_in[3];
    const float* b1   = (const float*)d_in[4];
    const float* W2   = (const float*)d_in[5];
    const float* b2   = (const float*)d_in[6];
    const float* emb0 = (const float*)d_in[7];
    const float* emb1 = (const float*)d_in[8];
    const float* fcW1 = (const float*)d_in[9];
    const float* fcb1 = (const float*)d_in[10];
    const float* fcW2 = (const float*)d_in[11];
    const float* fcb2 = (const float*)d_in[12];

    const int* src = ei;
    const int* dst = ei + NE;

    int gbE4 = (NE / 4 + 255) / 256;
    int gbG  = (2 * NN + 255) / 256;
    int gbW  = (NN * 32 + 255) / 256;

    k_count<<<gbE4, 256>>>(dst);
    k_scanA<<<NB, 1024>>>();
    k_scanB<<<1, 128>>>(emb0, emb1, fcW1, fcb1, fcW2, fcb2);
    k_gemm <<<gbG, 256>>>(x, W1, (float*)d_bufA);
    k_scanC<<<NB, 1024>>>();
    k_fill <<<gbE4, 256>>>(src, dst);
    k_agg  <<<gbW, 256>>>((const float*)d_bufA, b1, (float*)d_bufB, fcW1, 0);
    k_gemm <<<gbG, 256>>>((const float*)d_bufB, W2, (float*)d_bufA);
    k_agg  <<<gbW, 256>>>((const float*)d_bufA, b2, nullptr, fcW1, 1);
    k_edge <<<gbE4, 256>>>(src, dst, ea, (float4*)d_out);
}